// round 1
// baseline (speedup 1.0000x reference)
#include <cuda_runtime.h>
#include <cstdint>

#define NN      100000
#define NE      1600000
#define IN_DIM  128
#define HID     16
#define OUTD    40
#define QMAXF   255.0f

// ---------------------------------------------------------------------------
// Scratch (device globals — no allocation allowed)
// ---------------------------------------------------------------------------
__device__ float g_y [NN * HID];   // qdq(@W) output, reused each layer
__device__ float g_z1[NN * HID];   // spmm outputs
__device__ float g_z2[NN * HID];
__device__ float g_z3[NN * HID];

// ---------------------------------------------------------------------------
// Zero the three accumulator buffers (atomics add into them)
// ---------------------------------------------------------------------------
__global__ void __launch_bounds__(256) k_zero() {
    int t = blockIdx.x * blockDim.x + threadIdx.x;
    const int n4 = NN * HID / 4;           // 400000 float4
    if (t < n4) {
        float4 z = make_float4(0.f, 0.f, 0.f, 0.f);
        ((float4*)g_z1)[t] = z;
        ((float4*)g_z2)[t] = z;
        ((float4*)g_z3)[t] = z;
    }
}

// ---------------------------------------------------------------------------
// Halving warp reduction: 16 per-lane partials -> 16 warp sums.
// After stages, even lane l holds sum for j = (l>>1)&15.
// ---------------------------------------------------------------------------
template<int OFF, int V>
__device__ __forceinline__ void reduce_stage(float* acc, int lane) {
    const bool hi = (lane & OFF) != 0;
    float out[V];
#pragma unroll
    for (int m = 0; m < V; m++) {
        float keep = hi ? acc[m + V] : acc[m];
        float send = hi ? acc[m]     : acc[m + V];
        out[m] = keep + __shfl_xor_sync(0xffffffffu, send, OFF);
    }
#pragma unroll
    for (int m = 0; m < V; m++) acc[m] = out[m];
}

// ---------------------------------------------------------------------------
// Layer 1: per-row (128-dim) quant-dequant fused with x @ W1 -> y [N,16]
// One warp per row; W1 lives in registers (amortized over many rows).
// Lane owns k = lane*4 + i (i in 0..3), i.e. one contiguous float4 of the row.
// ---------------------------------------------------------------------------
__global__ void __launch_bounds__(128) k_layer1(
    const float* __restrict__ x, const float* __restrict__ noise,
    const float* __restrict__ W1, float* __restrict__ y)
{
    const int lane   = threadIdx.x & 31;
    const int warpId = (blockIdx.x * (blockDim.x >> 5)) + (threadIdx.x >> 5);
    const int nWarp  = gridDim.x * (blockDim.x >> 5);

    // W registers: w[i*4+jj] = W1[k][jj*4 .. jj*4+3], k = lane*4+i
    float4 w[16];
    const float4* W4 = (const float4*)W1;
#pragma unroll
    for (int i = 0; i < 4; i++)
#pragma unroll
        for (int jj = 0; jj < 4; jj++)
            w[i * 4 + jj] = __ldg(&W4[(lane * 4 + i) * 4 + jj]);

    for (int r = warpId; r < NN; r += nWarp) {
        float4 xv = __ldg(&((const float4*)x)[r * 32 + lane]);
        float4 nv = __ldg(&((const float4*)noise)[r * 32 + lane]);
        float xa[4] = {xv.x, xv.y, xv.z, xv.w};
        float na[4] = {nv.x, nv.y, nv.z, nv.w};

        float mn = fminf(fminf(xa[0], xa[1]), fminf(xa[2], xa[3]));
        float mx = fmaxf(fmaxf(xa[0], xa[1]), fmaxf(xa[2], xa[3]));
#pragma unroll
        for (int off = 16; off > 0; off >>= 1) {
            mn = fminf(mn, __shfl_xor_sync(0xffffffffu, mn, off));
            mx = fmaxf(mx, __shfl_xor_sync(0xffffffffu, mx, off));
        }

        float dq[4];
        if (mx > mn) {
            float rs = QMAXF / (mx - mn);           // matches reference ordering
#pragma unroll
            for (int i = 0; i < 4; i++) {
                float q = rintf((xa[i] - mn) * rs + na[i] - 0.5f);  // half-to-even
                q = fminf(fmaxf(q, 0.f), QMAXF);
                dq[i] = q / rs + mn;
            }
        } else {
#pragma unroll
            for (int i = 0; i < 4; i++) dq[i] = mn;
        }

        float acc[16];
#pragma unroll
        for (int j = 0; j < 16; j++) acc[j] = 0.f;
#pragma unroll
        for (int i = 0; i < 4; i++) {
#pragma unroll
            for (int jj = 0; jj < 4; jj++) {
                float4 ww = w[i * 4 + jj];
                acc[jj * 4 + 0] = fmaf(dq[i], ww.x, acc[jj * 4 + 0]);
                acc[jj * 4 + 1] = fmaf(dq[i], ww.y, acc[jj * 4 + 1]);
                acc[jj * 4 + 2] = fmaf(dq[i], ww.z, acc[jj * 4 + 2]);
                acc[jj * 4 + 3] = fmaf(dq[i], ww.w, acc[jj * 4 + 3]);
            }
        }

        reduce_stage<16, 8>(acc, lane);
        reduce_stage<8, 4>(acc, lane);
        reduce_stage<4, 2>(acc, lane);
        reduce_stage<2, 1>(acc, lane);
        float s = acc[0] + __shfl_xor_sync(0xffffffffu, acc[0], 1);
        if ((lane & 1) == 0)
            y[r * 16 + ((lane >> 1) & 15)] = s;
    }
}

// ---------------------------------------------------------------------------
// SpMM (16-dim): z[row[e]] += vals[e] * y[col[e]], via vector reductions.
// One thread per edge; 4x (float4 gather + red.global.add.v4.f32).
// ---------------------------------------------------------------------------
__global__ void __launch_bounds__(256) k_spmm(
    const int* __restrict__ row, const int* __restrict__ col,
    const float* __restrict__ vals,
    const float* __restrict__ y, float* __restrict__ z)
{
    int e = blockIdx.x * blockDim.x + threadIdx.x;
    if (e >= NE) return;
    int   r = __ldg(&row[e]);
    int   c = __ldg(&col[e]);
    float v = __ldg(&vals[e]);
    const float4* ysrc = (const float4*)y + (size_t)c * 4;
    float*        zdst = z + (size_t)r * 16;
#pragma unroll
    for (int ch = 0; ch < 4; ch++) {
        float4 a = __ldg(&ysrc[ch]);
        asm volatile("red.global.add.v4.f32 [%0], {%1,%2,%3,%4};"
                     :: "l"(zdst + ch * 4),
                        "f"(a.x * v), "f"(a.y * v), "f"(a.z * v), "f"(a.w * v)
                     : "memory");
    }
}

// ---------------------------------------------------------------------------
// Per-row 16-dim qdq helper (input already relu'd into xa[16])
// ---------------------------------------------------------------------------
__device__ __forceinline__ void qdq16(const float* xa, const float4* nrow, float* dq) {
    float mn = xa[0], mx = xa[0];
#pragma unroll
    for (int k = 1; k < 16; k++) { mn = fminf(mn, xa[k]); mx = fmaxf(mx, xa[k]); }
    if (mx > mn) {
        float rs = QMAXF / (mx - mn);
#pragma unroll
        for (int c = 0; c < 4; c++) {
            float4 nv = __ldg(&nrow[c]);
            float na[4] = {nv.x, nv.y, nv.z, nv.w};
#pragma unroll
            for (int i = 0; i < 4; i++) {
                float q = rintf((xa[c * 4 + i] - mn) * rs + na[i] - 0.5f);
                q = fminf(fmaxf(q, 0.f), QMAXF);
                dq[c * 4 + i] = q / rs + mn;
            }
        }
    } else {
#pragma unroll
        for (int k = 0; k < 16; k++) dq[k] = mn;
    }
}

// ---------------------------------------------------------------------------
// Mid layer: y = qdq(relu(z), noise) @ W (16x16). One thread per row.
// ---------------------------------------------------------------------------
__global__ void __launch_bounds__(256) k_mid(
    const float* __restrict__ z, const float* __restrict__ noise,
    const float* __restrict__ W, float* __restrict__ y)
{
    __shared__ float4 Ws[64];                        // 16x16
    if (threadIdx.x < 64) Ws[threadIdx.x] = ((const float4*)W)[threadIdx.x];
    __syncthreads();

    int r = blockIdx.x * blockDim.x + threadIdx.x;
    if (r >= NN) return;

    float xa[16];
#pragma unroll
    for (int c = 0; c < 4; c++) {
        float4 t = __ldg(&((const float4*)z)[r * 4 + c]);
        xa[c * 4 + 0] = fmaxf(t.x, 0.f); xa[c * 4 + 1] = fmaxf(t.y, 0.f);
        xa[c * 4 + 2] = fmaxf(t.z, 0.f); xa[c * 4 + 3] = fmaxf(t.w, 0.f);
    }
    float dq[16];
    qdq16(xa, (const float4*)noise + (size_t)r * 4, dq);

    float acc[16];
#pragma unroll
    for (int j = 0; j < 16; j++) acc[j] = 0.f;
#pragma unroll
    for (int k = 0; k < 16; k++) {
#pragma unroll
        for (int jj = 0; jj < 4; jj++) {
            float4 ww = Ws[k * 4 + jj];
            acc[jj * 4 + 0] = fmaf(dq[k], ww.x, acc[jj * 4 + 0]);
            acc[jj * 4 + 1] = fmaf(dq[k], ww.y, acc[jj * 4 + 1]);
            acc[jj * 4 + 2] = fmaf(dq[k], ww.z, acc[jj * 4 + 2]);
            acc[jj * 4 + 3] = fmaf(dq[k], ww.w, acc[jj * 4 + 3]);
        }
    }
#pragma unroll
    for (int jj = 0; jj < 4; jj++)
        ((float4*)y)[r * 4 + jj] =
            make_float4(acc[jj * 4], acc[jj * 4 + 1], acc[jj * 4 + 2], acc[jj * 4 + 3]);
}

// ---------------------------------------------------------------------------
// Layer-3 front: y = qdq(relu(z), noise)   (no matmul; W3 applied after spmm)
// ---------------------------------------------------------------------------
__global__ void __launch_bounds__(256) k_qdq_only(
    const float* __restrict__ z, const float* __restrict__ noise,
    float* __restrict__ y)
{
    int r = blockIdx.x * blockDim.x + threadIdx.x;
    if (r >= NN) return;
    float xa[16];
#pragma unroll
    for (int c = 0; c < 4; c++) {
        float4 t = __ldg(&((const float4*)z)[r * 4 + c]);
        xa[c * 4 + 0] = fmaxf(t.x, 0.f); xa[c * 4 + 1] = fmaxf(t.y, 0.f);
        xa[c * 4 + 2] = fmaxf(t.z, 0.f); xa[c * 4 + 3] = fmaxf(t.w, 0.f);
    }
    float dq[16];
    qdq16(xa, (const float4*)noise + (size_t)r * 4, dq);
#pragma unroll
    for (int jj = 0; jj < 4; jj++)
        ((float4*)y)[r * 4 + jj] =
            make_float4(dq[jj * 4], dq[jj * 4 + 1], dq[jj * 4 + 2], dq[jj * 4 + 3]);
}

// ---------------------------------------------------------------------------
// Tail: out = z3 @ W3  (16 x 40). One thread per row. No relu.
// ---------------------------------------------------------------------------
__global__ void __launch_bounds__(256) k_out(
    const float* __restrict__ z, const float* __restrict__ W3,
    float* __restrict__ out)
{
    __shared__ float4 Ws[160];                       // 16x40
    for (int i = threadIdx.x; i < 160; i += blockDim.x)
        Ws[i] = ((const float4*)W3)[i];
    __syncthreads();

    int r = blockIdx.x * blockDim.x + threadIdx.x;
    if (r >= NN) return;

    float xa[16];
#pragma unroll
    for (int c = 0; c < 4; c++) {
        float4 t = __ldg(&((const float4*)z)[r * 4 + c]);
        xa[c * 4 + 0] = t.x; xa[c * 4 + 1] = t.y;
        xa[c * 4 + 2] = t.z; xa[c * 4 + 3] = t.w;
    }
    float4 acc[10];
#pragma unroll
    for (int jj = 0; jj < 10; jj++) acc[jj] = make_float4(0.f, 0.f, 0.f, 0.f);
#pragma unroll
    for (int k = 0; k < 16; k++) {
#pragma unroll
        for (int jj = 0; jj < 10; jj++) {
            float4 ww = Ws[k * 10 + jj];
            acc[jj].x = fmaf(xa[k], ww.x, acc[jj].x);
            acc[jj].y = fmaf(xa[k], ww.y, acc[jj].y);
            acc[jj].z = fmaf(xa[k], ww.z, acc[jj].z);
            acc[jj].w = fmaf(xa[k], ww.w, acc[jj].w);
        }
    }
#pragma unroll
    for (int jj = 0; jj < 10; jj++)
        ((float4*)out)[(size_t)r * 10 + jj] = acc[jj];
}

// ---------------------------------------------------------------------------
extern "C" void kernel_launch(void* const* d_in, const int* in_sizes, int n_in,
                              void* d_out, int out_size)
{
    const float* features = (const float*)d_in[0];
    const int*   row      = (const int*)  d_in[1];
    const int*   col      = (const int*)  d_in[2];
    const float* vals     = (const float*)d_in[3];
    const float* W1       = (const float*)d_in[4];
    const float* W2       = (const float*)d_in[5];
    const float* W3       = (const float*)d_in[6];
    const float* noise1   = (const float*)d_in[7];
    const float* noise2   = (const float*)d_in[8];
    const float* noise3   = (const float*)d_in[9];

    float *py, *pz1, *pz2, *pz3;
    cudaGetSymbolAddress((void**)&py,  g_y);
    cudaGetSymbolAddress((void**)&pz1, g_z1);
    cudaGetSymbolAddress((void**)&pz2, g_z2);
    cudaGetSymbolAddress((void**)&pz3, g_z3);

    const int rowBlocks  = (NN + 255) / 256;         // 391
    const int edgeBlocks = (NE + 255) / 256;         // 6250
    const int zeroBlocks = (NN * HID / 4 + 255) / 256;

    k_zero  <<<zeroBlocks, 256>>>();
    k_layer1<<<740, 128>>>(features, noise1, W1, py);
    k_spmm  <<<edgeBlocks, 256>>>(row, col, vals, py, pz1);
    k_mid   <<<rowBlocks, 256>>>(pz1, noise2, W2, py);
    k_spmm  <<<edgeBlocks, 256>>>(row, col, vals, py, pz2);
    k_qdq_only<<<rowBlocks, 256>>>(pz2, noise3, py);
    k_spmm  <<<edgeBlocks, 256>>>(row, col, vals, py, pz3);
    k_out   <<<rowBlocks, 256>>>(pz3, W3, (float*)d_out);
}

// round 2
// speedup vs baseline: 1.1632x; 1.1632x over previous
#include <cuda_runtime.h>
#include <cstdint>

#define NN      100000
#define NE      1600000
#define HID     16
#define OUTD    40
#define QMAXF   255.0f

// ---------------------------------------------------------------------------
// Scratch (device globals — allocation is forbidden)
// ---------------------------------------------------------------------------
__device__ float g_ya[NN * HID];        // ping
__device__ float g_yb[NN * HID];        // pong
__device__ int2  g_ecv[NE];             // row-sorted (col, val) pairs
__device__ int   g_cnt[NN];
__device__ int   g_cur[NN];
__device__ int   g_off[NN + 1];
__device__ int   g_bsum[128];
__device__ int   g_boff[128];

// ---------------------------------------------------------------------------
// CSR build: clear -> hist -> scan(3 phases) -> scatter
// ---------------------------------------------------------------------------
__global__ void __launch_bounds__(256) k_clear() {
    int t = blockIdx.x * 256 + threadIdx.x;
    if (t < NN) g_cnt[t] = 0;
}

__global__ void __launch_bounds__(256) k_hist(const int* __restrict__ row) {
    int e = blockIdx.x * 256 + threadIdx.x;
    if (e < NE) atomicAdd(&g_cnt[__ldg(&row[e])], 1);
}

// 98 blocks x 1024 counts each
__global__ void __launch_bounds__(256) k_scan1() {
    int b = blockIdx.x, t = threadIdx.x;
    int base = b * 1024 + t * 4;
    int s = 0;
#pragma unroll
    for (int i = 0; i < 4; i++) { int idx = base + i; if (idx < NN) s += g_cnt[idx]; }
    __shared__ int sh[256];
    sh[t] = s; __syncthreads();
#pragma unroll
    for (int o = 128; o > 0; o >>= 1) {
        if (t < o) sh[t] += sh[t + o];
        __syncthreads();
    }
    if (t == 0) g_bsum[b] = sh[0];
}

__global__ void __launch_bounds__(128) k_scan2() {
    int t = threadIdx.x;
    int v = (t < 98) ? g_bsum[t] : 0;
    __shared__ int sh[128];
    sh[t] = v; __syncthreads();
#pragma unroll
    for (int o = 1; o < 128; o <<= 1) {
        int u = (t >= o) ? sh[t - o] : 0;
        __syncthreads();
        sh[t] += u;
        __syncthreads();
    }
    if (t < 98) g_boff[t] = sh[t] - v;   // exclusive
}

__global__ void __launch_bounds__(256) k_scan3() {
    int b = blockIdx.x, t = threadIdx.x;
    int base = b * 1024 + t * 4;
    int c[4]; int tot = 0;
#pragma unroll
    for (int i = 0; i < 4; i++) {
        int idx = base + i;
        c[i] = (idx < NN) ? g_cnt[idx] : 0;
        tot += c[i];
    }
    __shared__ int sh[256];
    sh[t] = tot; __syncthreads();
#pragma unroll
    for (int o = 1; o < 256; o <<= 1) {
        int u = (t >= o) ? sh[t - o] : 0;
        __syncthreads();
        sh[t] += u;
        __syncthreads();
    }
    int run = sh[t] - tot + g_boff[b];   // exclusive prefix for this thread
#pragma unroll
    for (int i = 0; i < 4; i++) {
        int idx = base + i;
        if (idx < NN) { g_off[idx] = run; g_cur[idx] = run; run += c[i]; }
    }
    if (b == 0 && t == 0) g_off[NN] = NE;
}

__global__ void __launch_bounds__(256) k_scatter(
    const int* __restrict__ row, const int* __restrict__ col,
    const float* __restrict__ vals)
{
    int e = blockIdx.x * 256 + threadIdx.x;
    if (e >= NE) return;
    int r = __ldg(&row[e]);
    int p = atomicAdd(&g_cur[r], 1);
    g_ecv[p] = make_int2(__ldg(&col[e]), __float_as_int(__ldg(&vals[e])));
}

// ---------------------------------------------------------------------------
// Layer 1: per-row (128-dim) qdq fused with x @ W1 -> y [N,16]. Warp per row.
// ---------------------------------------------------------------------------
template<int OFF, int V>
__device__ __forceinline__ void reduce_stage(float* acc, int lane) {
    const bool hi = (lane & OFF) != 0;
    float out[V];
#pragma unroll
    for (int m = 0; m < V; m++) {
        float keep = hi ? acc[m + V] : acc[m];
        float send = hi ? acc[m]     : acc[m + V];
        out[m] = keep + __shfl_xor_sync(0xffffffffu, send, OFF);
    }
#pragma unroll
    for (int m = 0; m < V; m++) acc[m] = out[m];
}

__global__ void __launch_bounds__(128) k_layer1(
    const float* __restrict__ x, const float* __restrict__ noise,
    const float* __restrict__ W1, float* __restrict__ y)
{
    const int lane   = threadIdx.x & 31;
    const int warpId = (blockIdx.x * (blockDim.x >> 5)) + (threadIdx.x >> 5);
    const int nWarp  = gridDim.x * (blockDim.x >> 5);

    float4 w[16];
    const float4* W4 = (const float4*)W1;
#pragma unroll
    for (int i = 0; i < 4; i++)
#pragma unroll
        for (int jj = 0; jj < 4; jj++)
            w[i * 4 + jj] = __ldg(&W4[(lane * 4 + i) * 4 + jj]);

    for (int r = warpId; r < NN; r += nWarp) {
        float4 xv = __ldg(&((const float4*)x)[r * 32 + lane]);
        float4 nv = __ldg(&((const float4*)noise)[r * 32 + lane]);
        float xa[4] = {xv.x, xv.y, xv.z, xv.w};
        float na[4] = {nv.x, nv.y, nv.z, nv.w};

        float mn = fminf(fminf(xa[0], xa[1]), fminf(xa[2], xa[3]));
        float mx = fmaxf(fmaxf(xa[0], xa[1]), fmaxf(xa[2], xa[3]));
#pragma unroll
        for (int off = 16; off > 0; off >>= 1) {
            mn = fminf(mn, __shfl_xor_sync(0xffffffffu, mn, off));
            mx = fmaxf(mx, __shfl_xor_sync(0xffffffffu, mx, off));
        }

        float dq[4];
        if (mx > mn) {
            float rs = QMAXF / (mx - mn);
#pragma unroll
            for (int i = 0; i < 4; i++) {
                float q = rintf((xa[i] - mn) * rs + na[i] - 0.5f);
                q = fminf(fmaxf(q, 0.f), QMAXF);
                dq[i] = q / rs + mn;
            }
        } else {
#pragma unroll
            for (int i = 0; i < 4; i++) dq[i] = mn;
        }

        float acc[16];
#pragma unroll
        for (int j = 0; j < 16; j++) acc[j] = 0.f;
#pragma unroll
        for (int i = 0; i < 4; i++) {
#pragma unroll
            for (int jj = 0; jj < 4; jj++) {
                float4 ww = w[i * 4 + jj];
                acc[jj * 4 + 0] = fmaf(dq[i], ww.x, acc[jj * 4 + 0]);
                acc[jj * 4 + 1] = fmaf(dq[i], ww.y, acc[jj * 4 + 1]);
                acc[jj * 4 + 2] = fmaf(dq[i], ww.z, acc[jj * 4 + 2]);
                acc[jj * 4 + 3] = fmaf(dq[i], ww.w, acc[jj * 4 + 3]);
            }
        }
        reduce_stage<16, 8>(acc, lane);
        reduce_stage<8, 4>(acc, lane);
        reduce_stage<4, 2>(acc, lane);
        reduce_stage<2, 1>(acc, lane);
        float s = acc[0] + __shfl_xor_sync(0xffffffffu, acc[0], 1);
        if ((lane & 1) == 0)
            y[r * 16 + ((lane >> 1) & 15)] = s;
    }
}

// ---------------------------------------------------------------------------
// CSR row-gather SpMM, half-warp (16 lanes = 16 dims) per row, fused epilogue:
//   EP=1: relu + qdq(noise) + @W(16x16)  -> y       (after layer-1 / layer-2 spmm)
//   EP=2: relu + qdq(noise)              -> y       (before layer-3 spmm)
//   EP=3: @W3(16x40)                     -> out     (final)
// Grid is exact: 6250 blocks x 8 warps x 2 rows = 100000 rows.
// ---------------------------------------------------------------------------
template<int EP>
__global__ void __launch_bounds__(256) k_spmm(
    const float* __restrict__ yin, const float* __restrict__ noise,
    const float* __restrict__ W, float* __restrict__ out)
{
    __shared__ float Ws[16 * 40];
    if (EP == 1) { if (threadIdx.x < 256) Ws[threadIdx.x] = W[threadIdx.x]; }
    if (EP == 3) { for (int i = threadIdx.x; i < 640; i += 256) Ws[i] = W[i]; }
    if (EP != 2) __syncthreads();

    const int lane = threadIdx.x & 31;
    const int l    = lane & 15;                         // dim index
    const int r    = (blockIdx.x * 8 + (threadIdx.x >> 5)) * 2 + (lane >> 4);

    int       i = __ldg(&g_off[r]);
    const int e = __ldg(&g_off[r + 1]);
    float acc = 0.f;

    for (; i + 3 < e; i += 4) {
        int2 c0 = __ldg(&g_ecv[i]);
        int2 c1 = __ldg(&g_ecv[i + 1]);
        int2 c2 = __ldg(&g_ecv[i + 2]);
        int2 c3 = __ldg(&g_ecv[i + 3]);
        float y0 = __ldg(&yin[c0.x * 16 + l]);
        float y1 = __ldg(&yin[c1.x * 16 + l]);
        float y2 = __ldg(&yin[c2.x * 16 + l]);
        float y3 = __ldg(&yin[c3.x * 16 + l]);
        acc = fmaf(__int_as_float(c0.y), y0, acc);
        acc = fmaf(__int_as_float(c1.y), y1, acc);
        acc = fmaf(__int_as_float(c2.y), y2, acc);
        acc = fmaf(__int_as_float(c3.y), y3, acc);
    }
    for (; i < e; i++) {
        int2 cv = __ldg(&g_ecv[i]);
        acc = fmaf(__int_as_float(cv.y), __ldg(&yin[cv.x * 16 + l]), acc);
    }

    if (EP == 3) {
        float a0 = 0.f, a1 = 0.f, a2 = 0.f;
#pragma unroll
        for (int j = 0; j < 16; j++) {
            float d = __shfl_sync(0xffffffffu, acc, (lane & 16) + j);
            a0 = fmaf(d, Ws[j * 40 + l], a0);
            a1 = fmaf(d, Ws[j * 40 + l + 16], a1);
            if (l < 8) a2 = fmaf(d, Ws[j * 40 + l + 32], a2);
        }
        out[r * 40 + l]      = a0;
        out[r * 40 + l + 16] = a1;
        if (l < 8) out[r * 40 + l + 32] = a2;
    } else {
        float x = fmaxf(acc, 0.f);
        float mn = x, mx = x;
#pragma unroll
        for (int o = 8; o > 0; o >>= 1) {
            mn = fminf(mn, __shfl_xor_sync(0xffffffffu, mn, o));
            mx = fmaxf(mx, __shfl_xor_sync(0xffffffffu, mx, o));
        }
        float dq;
        if (mx > mn) {
            float rs = QMAXF / (mx - mn);
            float nz = __ldg(&noise[r * 16 + l]);
            float q  = rintf((x - mn) * rs + nz - 0.5f);
            q = fminf(fmaxf(q, 0.f), QMAXF);
            dq = q / rs + mn;
        } else dq = mn;

        if (EP == 2) {
            out[r * 16 + l] = dq;
        } else {
            float a = 0.f;
#pragma unroll
            for (int j = 0; j < 16; j++) {
                float d = __shfl_sync(0xffffffffu, dq, (lane & 16) + j);
                a = fmaf(d, Ws[j * 16 + l], a);
            }
            out[r * 16 + l] = a;
        }
    }
}

// ---------------------------------------------------------------------------
extern "C" void kernel_launch(void* const* d_in, const int* in_sizes, int n_in,
                              void* d_out, int out_size)
{
    const float* features = (const float*)d_in[0];
    const int*   row      = (const int*)  d_in[1];
    const int*   col      = (const int*)  d_in[2];
    const float* vals     = (const float*)d_in[3];
    const float* W1       = (const float*)d_in[4];
    const float* W2       = (const float*)d_in[5];
    const float* W3       = (const float*)d_in[6];
    const float* noise1   = (const float*)d_in[7];
    const float* noise2   = (const float*)d_in[8];
    const float* noise3   = (const float*)d_in[9];

    float *pya, *pyb;
    cudaGetSymbolAddress((void**)&pya, g_ya);
    cudaGetSymbolAddress((void**)&pyb, g_yb);

    const int nodeBlocks = (NN + 255) / 256;     // 391
    const int edgeBlocks = (NE + 255) / 256;     // 6250
    const int scanBlocks = (NN + 1023) / 1024;   // 98
    const int spmmBlocks = NN / 32;              // 3125? -> rows: blocks*8 warps*2 rows

    // CSR build
    k_clear  <<<nodeBlocks, 256>>>();
    k_hist   <<<edgeBlocks, 256>>>(row);
    k_scan1  <<<scanBlocks, 256>>>();
    k_scan2  <<<1, 128>>>();
    k_scan3  <<<scanBlocks, 256>>>();
    k_scatter<<<edgeBlocks, 256>>>(row, col, vals);

    // Layer 1 dense front
    k_layer1<<<740, 128>>>(features, noise1, W1, pya);

    // Fused SpMM pipeline (6250 blocks = exactly 100000 rows)
    k_spmm<1><<<NN / 16, 256>>>(pya, noise2, W2, pyb);
    k_spmm<2><<<NN / 16, 256>>>(pyb, noise3, nullptr, pya);
    k_spmm<3><<<NN / 16, 256>>>(pya, nullptr, W3, (float*)d_out);
}